// round 8
// baseline (speedup 1.0000x reference)
#include <cuda_runtime.h>
#include <cstdint>

#define Bb   8
#define Tt   4096
#define Dd   768
#define Hh   12
#define HDd  64
#define KSp  32
#define D3   2304

#define NSEG 16
#define TSEG 256
#define TCH  16
#define CHUNKS (TSEG / TCH)   // 16

typedef unsigned long long u64;

// ---------------- scratch ----------------
__device__ float g_partial[NSEG * Bb * KSp * Dd];   // 12.6 MB (L2-resident)
__device__ float g_xs[Bb * KSp * Dd];
__device__ float g_qkv[Bb * KSp * D3];
__device__ float g_y[Bb * KSp * Dd];

// ---------------- packed f32x2 ----------------
__device__ __forceinline__ u64 pk2(float lo, float hi) {
    u64 r;
    asm("mov.b64 %0, {%1, %2};" : "=l"(r) : "f"(lo), "f"(hi));
    return r;
}
__device__ __forceinline__ void fma2(u64& d, u64 a, u64 b) {
    asm("fma.rn.f32x2 %0, %1, %2, %0;" : "+l"(d) : "l"(a), "l"(b));
}

__global__ void k_nop() {}

// =====================================================================
// K1: partial[seg][b][k][d] = sum_{t in seg} S[b,t,k] * x[b,t,d]
// grid (3 d-tiles, NSEG, B) x 256 thr. Thread tile 8k x 4d:
// per t: 1 LDS.128 x (4 crossbar cyc/warp) + 2 broadcast S vs 16 FFMA2
// (8 FMA cyc) -> FMA-bound. acc = 32 regs -> 3 blocks/SM (50% occ).
// =====================================================================
__global__ void __launch_bounds__(256, 3) k_project(const float* __restrict__ x,
                                                    const float* __restrict__ S) {
    const int d0  = blockIdx.x * 256;
    const int t0  = blockIdx.y * TSEG;
    const int b   = blockIdx.z;
    const int tid = threadIdx.x;

    __shared__ float Ssm[TSEG][KSp];   // 32 KB
    __shared__ float Xsm[TCH][256];    // 16 KB  (48 KB total)

    const float* xbase = x + ((size_t)b * Tt + t0) * Dd + d0;
    const int lr = tid >> 6;           // 0..3
    const int lc = tid & 63;           // 0..63

    // prefetch x chunk 0 into registers
    float4 xr[4];
#pragma unroll
    for (int i = 0; i < 4; i++)
        xr[i] = *reinterpret_cast<const float4*>(
            xbase + (size_t)(lr + i * 4) * Dd + lc * 4);

    // S tile: 256 rows x 32 floats = 2048 float4, 8 per thread
    {
        const float4* sg = reinterpret_cast<const float4*>(
            S + ((size_t)b * Tt + t0) * KSp);
        float4* ss = reinterpret_cast<float4*>(&Ssm[0][0]);
#pragma unroll
        for (int i = 0; i < 8; i++) ss[tid + i * 256] = sg[tid + i * 256];
    }

    const int kq = tid >> 6;           // 0..3 -> k base kq*8 (warp-uniform)
    const int dq = tid & 63;           // 0..63 -> d cols dq*4..dq*4+3

    u64 acc[8][2];
#pragma unroll
    for (int i = 0; i < 8; i++) { acc[i][0] = 0ull; acc[i][1] = 0ull; }

    for (int ch = 0; ch < CHUNKS; ch++) {
        // commit staged chunk to smem
#pragma unroll
        for (int i = 0; i < 4; i++)
            *reinterpret_cast<float4*>(&Xsm[lr + i * 4][lc * 4]) = xr[i];
        __syncthreads();
        // prefetch next chunk (hides behind compute)
        if (ch + 1 < CHUNKS) {
            const float* nb = xbase + (size_t)(ch + 1) * TCH * Dd;
#pragma unroll
            for (int i = 0; i < 4; i++)
                xr[i] = *reinterpret_cast<const float4*>(
                    nb + (size_t)(lr + i * 4) * Dd + lc * 4);
        }
#pragma unroll
        for (int t = 0; t < TCH; t++) {
            ulonglong2 xa = *reinterpret_cast<const ulonglong2*>(&Xsm[t][dq * 4]);
            // k 0..3 of this thread's 8
            {
                float4 sa = *reinterpret_cast<const float4*>(&Ssm[ch * TCH + t][kq * 8]);
                u64 s;
                s = pk2(sa.x, sa.x); fma2(acc[0][0], s, xa.x); fma2(acc[0][1], s, xa.y);
                s = pk2(sa.y, sa.y); fma2(acc[1][0], s, xa.x); fma2(acc[1][1], s, xa.y);
                s = pk2(sa.z, sa.z); fma2(acc[2][0], s, xa.x); fma2(acc[2][1], s, xa.y);
                s = pk2(sa.w, sa.w); fma2(acc[3][0], s, xa.x); fma2(acc[3][1], s, xa.y);
            }
            // k 4..7
            {
                float4 sb = *reinterpret_cast<const float4*>(&Ssm[ch * TCH + t][kq * 8 + 4]);
                u64 s;
                s = pk2(sb.x, sb.x); fma2(acc[4][0], s, xa.x); fma2(acc[4][1], s, xa.y);
                s = pk2(sb.y, sb.y); fma2(acc[5][0], s, xa.x); fma2(acc[5][1], s, xa.y);
                s = pk2(sb.z, sb.z); fma2(acc[6][0], s, xa.x); fma2(acc[6][1], s, xa.y);
                s = pk2(sb.w, sb.w); fma2(acc[7][0], s, xa.x); fma2(acc[7][1], s, xa.y);
            }
        }
        __syncthreads();
    }

#pragma unroll
    for (int kk = 0; kk < 8; kk++) {
        ulonglong2 o; o.x = acc[kk][0]; o.y = acc[kk][1];
        *reinterpret_cast<ulonglong2*>(
            &g_partial[(((size_t)blockIdx.y * Bb + b) * KSp + kq * 8 + kk) * Dd + d0 + dq * 4]) = o;
    }
}

// =====================================================================
// K2: xs = sum over 16 segments (L2-resident partials)
// =====================================================================
__global__ void k_reduce() {
    const int i = blockIdx.x * blockDim.x + threadIdx.x;
    const int stride4 = (Bb * KSp * Dd) / 4;
    const float4* p = reinterpret_cast<const float4*>(g_partial);
    float4 s = make_float4(0.f, 0.f, 0.f, 0.f);
#pragma unroll
    for (int seg = 0; seg < NSEG; seg++) {
        float4 v = p[(size_t)seg * stride4 + i];
        s.x += v.x; s.y += v.y; s.z += v.z; s.w += v.w;
    }
    reinterpret_cast<float4*>(g_xs)[i] = s;
}

// =====================================================================
// K3: qkv[256,2304] = xs[256,768] * w_qkv[2304,768]^T
// tiles 64m x 64n, BK=32, 256 thr, thread tile 4m x 4n, prefetched.
// =====================================================================
__global__ void __launch_bounds__(256) k_gemm1(const float* __restrict__ W) {
    const int n0 = blockIdx.x * 64;
    const int m0 = blockIdx.y * 64;
    const int tid = threadIdx.x;
    const int tn = tid & 15, tm = tid >> 4;
    const int lr = tid >> 3, lc = tid & 7;

    __shared__ float Asm[32][68];
    __shared__ float Bsm[32][68];

    float4 ar[2], br[2];
#pragma unroll
    for (int i = 0; i < 2; i++) {
        ar[i] = *reinterpret_cast<const float4*>(
            &g_xs[(size_t)(m0 + lr + i * 32) * Dd + lc * 4]);
        br[i] = *reinterpret_cast<const float4*>(
            &W[(size_t)(n0 + lr + i * 32) * Dd + lc * 4]);
    }

    u64 acc[4][2];
#pragma unroll
    for (int r = 0; r < 4; r++) { acc[r][0] = 0ull; acc[r][1] = 0ull; }

    for (int d0 = 0; d0 < Dd; d0 += 32) {
#pragma unroll
        for (int i = 0; i < 2; i++) {
            int r = lr + i * 32;
            Asm[lc * 4 + 0][r] = ar[i].x; Asm[lc * 4 + 1][r] = ar[i].y;
            Asm[lc * 4 + 2][r] = ar[i].z; Asm[lc * 4 + 3][r] = ar[i].w;
            Bsm[lc * 4 + 0][r] = br[i].x; Bsm[lc * 4 + 1][r] = br[i].y;
            Bsm[lc * 4 + 2][r] = br[i].z; Bsm[lc * 4 + 3][r] = br[i].w;
        }
        __syncthreads();
        if (d0 + 32 < Dd) {
#pragma unroll
            for (int i = 0; i < 2; i++) {
                ar[i] = *reinterpret_cast<const float4*>(
                    &g_xs[(size_t)(m0 + lr + i * 32) * Dd + d0 + 32 + lc * 4]);
                br[i] = *reinterpret_cast<const float4*>(
                    &W[(size_t)(n0 + lr + i * 32) * Dd + d0 + 32 + lc * 4]);
            }
        }
#pragma unroll
        for (int k = 0; k < 32; k++) {
            float4 av = *reinterpret_cast<const float4*>(&Asm[k][tm * 4]);
            ulonglong2 bv = *reinterpret_cast<const ulonglong2*>(&Bsm[k][tn * 4]);
            u64 a0 = pk2(av.x, av.x), a1 = pk2(av.y, av.y);
            u64 a2 = pk2(av.z, av.z), a3 = pk2(av.w, av.w);
            fma2(acc[0][0], a0, bv.x); fma2(acc[0][1], a0, bv.y);
            fma2(acc[1][0], a1, bv.x); fma2(acc[1][1], a1, bv.y);
            fma2(acc[2][0], a2, bv.x); fma2(acc[2][1], a2, bv.y);
            fma2(acc[3][0], a3, bv.x); fma2(acc[3][1], a3, bv.y);
        }
        __syncthreads();
    }

#pragma unroll
    for (int r = 0; r < 4; r++) {
        ulonglong2 o; o.x = acc[r][0]; o.y = acc[r][1];
        *reinterpret_cast<ulonglong2*>(
            &g_qkv[(size_t)(m0 + tm * 4 + r) * D3 + n0 + tn * 4]) = o;
    }
}

// =====================================================================
// K4: fused FHN + gemm2:  y[256,768] = (fv ⊙ v_spec) * w_out^T
// grid (12 n-tiles, 8 b) x 128 thr. Prologue computes fv[32][12]/block.
// =====================================================================
__global__ void __launch_bounds__(128) k_gemm2(const float* __restrict__ W,
                                               const float* __restrict__ sfilter) {
    const int n0 = blockIdx.x * 64;
    const int bb = blockIdx.y;
    const int tid = threadIdx.x;
    const int tn = tid & 15, tm = tid >> 4;
    const int lr = tid >> 3, lc = tid & 7;

    __shared__ float Asm[32][36];
    __shared__ float Bsm[32][68];
    __shared__ float fvs[KSp][Hh];

#pragma unroll
    for (int p = 0; p < 3; p++) {
        int idx = tid + p * 128;
        int m = idx & 31, h = idx >> 5;
        const float4* qp = reinterpret_cast<const float4*>(
            g_qkv + (size_t)(bb * KSp + m) * D3 + h * HDd);
        const float4* kp = reinterpret_cast<const float4*>(
            g_qkv + (size_t)(bb * KSp + m) * D3 + Dd + h * HDd);
        float s = 0.f;
#pragma unroll
        for (int j = 0; j < 16; j++) {
            float4 a = qp[j], c = kp[j];
            s += a.x * c.x + a.y * c.y + a.z * c.z + a.w * c.w;
        }
        float filt = 1.f / (1.f + expf(-sfilter[h * 32 + m]));
        float attn = s * 0.125f * filt;

        float aa = fabsf(attn);
        float scale = fmaxf(aa, 1e-6f);
        float sn = attn / scale;
        float gate = 1.f / (1.f + expf(-(aa - 0.5f) * 10.f));
        float I = sn * (0.1f + 0.9f * gate);
        const float alpha = 1.0f / 12.5f;
        const float denom = 1.0f + alpha * 0.8f;
        float v = 0.f, w = 0.f;
#pragma unroll
        for (int st = 0; st < 2; st++) {
            float dv = v - (v * v * v) * (1.f / 3.f) - w + I;
            float vn = v + dv;
            float wn = (w + (vn + 0.7f) * alpha) / denom;
            v = fminf(fmaxf(vn, -3.f), 3.f);
            w = fminf(fmaxf(wn, -3.f), 3.f);
        }
        fvs[m][h] = v * scale;
    }

    float4 ar[2], br[4];
#pragma unroll
    for (int i = 0; i < 2; i++)
        ar[i] = *reinterpret_cast<const float4*>(
            &g_qkv[(size_t)(bb * KSp + lr + i * 16) * D3 + 2 * Dd + lc * 4]);
#pragma unroll
    for (int i = 0; i < 4; i++)
        br[i] = *reinterpret_cast<const float4*>(
            &W[(size_t)(n0 + lr + i * 16) * Dd + lc * 4]);
    __syncthreads();

    u64 acc[4][2];
#pragma unroll
    for (int r = 0; r < 4; r++) { acc[r][0] = 0ull; acc[r][1] = 0ull; }

    for (int d0 = 0; d0 < Dd; d0 += 32) {
        const int hh = d0 >> 6;
#pragma unroll
        for (int i = 0; i < 2; i++) {
            int r = lr + i * 16;
            float f = fvs[r][hh];
            Asm[lc * 4 + 0][r] = ar[i].x * f; Asm[lc * 4 + 1][r] = ar[i].y * f;
            Asm[lc * 4 + 2][r] = ar[i].z * f; Asm[lc * 4 + 3][r] = ar[i].w * f;
        }
#pragma unroll
        for (int i = 0; i < 4; i++) {
            int r = lr + i * 16;
            Bsm[lc * 4 + 0][r] = br[i].x; Bsm[lc * 4 + 1][r] = br[i].y;
            Bsm[lc * 4 + 2][r] = br[i].z; Bsm[lc * 4 + 3][r] = br[i].w;
        }
        __syncthreads();
        if (d0 + 32 < Dd) {
#pragma unroll
            for (int i = 0; i < 2; i++)
                ar[i] = *reinterpret_cast<const float4*>(
                    &g_qkv[(size_t)(bb * KSp + lr + i * 16) * D3 + 2 * Dd + d0 + 32 + lc * 4]);
#pragma unroll
            for (int i = 0; i < 4; i++)
                br[i] = *reinterpret_cast<const float4*>(
                    &W[(size_t)(n0 + lr + i * 16) * Dd + d0 + 32 + lc * 4]);
        }
#pragma unroll
        for (int k = 0; k < 32; k++) {
            float4 av = *reinterpret_cast<const float4*>(&Asm[k][tm * 4]);
            ulonglong2 bv = *reinterpret_cast<const ulonglong2*>(&Bsm[k][tn * 4]);
            u64 a0 = pk2(av.x, av.x), a1 = pk2(av.y, av.y);
            u64 a2 = pk2(av.z, av.z), a3 = pk2(av.w, av.w);
            fma2(acc[0][0], a0, bv.x); fma2(acc[0][1], a0, bv.y);
            fma2(acc[1][0], a1, bv.x); fma2(acc[1][1], a1, bv.y);
            fma2(acc[2][0], a2, bv.x); fma2(acc[2][1], a2, bv.y);
            fma2(acc[3][0], a3, bv.x); fma2(acc[3][1], a3, bv.y);
        }
        __syncthreads();
    }

#pragma unroll
    for (int r = 0; r < 4; r++) {
        ulonglong2 o; o.x = acc[r][0]; o.y = acc[r][1];
        *reinterpret_cast<ulonglong2*>(
            &g_y[(size_t)(bb * KSp + tm * 4 + r) * Dd + n0 + tn * 4]) = o;
    }
}

// =====================================================================
// K5: out tile [128t x 128e] = S * y, thread tile 8t x 8e,
// S read as row-major float4 (broadcast within half-warp).
// =====================================================================
__global__ void __launch_bounds__(256, 2) k_expand(const float* __restrict__ S,
                                                   float* __restrict__ out) {
    const int e0  = blockIdx.x * 128;
    const int t0  = blockIdx.y * 128;
    const int b   = blockIdx.z;
    const int tid = threadIdx.x;

    __shared__ float Ssm[128][36];     // 18 KB
    __shared__ float Ysm[KSp][132];    // 16.9 KB

    {
        const float4* sg = reinterpret_cast<const float4*>(
            S + ((size_t)b * Tt + t0) * KSp);
#pragma unroll
        for (int i = 0; i < 4; i++) {
            int n = tid + i * 256;
            float4 v = sg[n];
            *reinterpret_cast<float4*>(&Ssm[n >> 3][(n & 7) * 4]) = v;
        }
#pragma unroll
        for (int i = 0; i < 4; i++) {
            int n = tid + i * 256;
            int r = n >> 5, c = n & 31;
            *reinterpret_cast<float4*>(&Ysm[r][c * 4]) =
                *reinterpret_cast<const float4*>(
                    &g_y[((size_t)b * KSp + r) * Dd + e0 + c * 4]);
        }
    }
    __syncthreads();

    const int i0 = (tid >> 4) * 8;
    const int j0 = tid & 15;

    u64 acc[8][4];
#pragma unroll
    for (int i = 0; i < 8; i++)
#pragma unroll
        for (int j = 0; j < 4; j++) acc[i][j] = 0ull;

#pragma unroll
    for (int kc = 0; kc < 8; kc++) {
        float4 sv[8];
#pragma unroll
        for (int i = 0; i < 8; i++)
            sv[i] = *reinterpret_cast<const float4*>(&Ssm[i0 + i][kc * 4]);
#pragma unroll
        for (int kk = 0; kk < 4; kk++) {
            int k = kc * 4 + kk;
            ulonglong2 ya = *reinterpret_cast<const ulonglong2*>(&Ysm[k][j0 * 4]);
            ulonglong2 yb = *reinterpret_cast<const ulonglong2*>(&Ysm[k][64 + j0 * 4]);
#pragma unroll
            for (int i = 0; i < 8; i++) {
                float s = (kk == 0) ? sv[i].x : (kk == 1) ? sv[i].y
                        : (kk == 2) ? sv[i].z : sv[i].w;
                u64 sd = pk2(s, s);
                fma2(acc[i][0], sd, ya.x); fma2(acc[i][1], sd, ya.y);
                fma2(acc[i][2], sd, yb.x); fma2(acc[i][3], sd, yb.y);
            }
        }
    }

    float* ob = out + ((size_t)b * Tt + t0 + i0) * Dd + e0;
#pragma unroll
    for (int i = 0; i < 8; i++) {
        ulonglong2 o1, o2;
        o1.x = acc[i][0]; o1.y = acc[i][1];
        o2.x = acc[i][2]; o2.y = acc[i][3];
        *reinterpret_cast<ulonglong2*>(ob + (size_t)i * Dd + j0 * 4) = o1;
        *reinterpret_cast<ulonglong2*>(ob + (size_t)i * Dd + 64 + j0 * 4) = o2;
    }
}

// =====================================================================
extern "C" void kernel_launch(void* const* d_in, const int* in_sizes, int n_in,
                              void* d_out, int out_size) {
    const float* x       = (const float*)d_in[0];
    const float* S       = (const float*)d_in[1];
    const float* w_qkv   = (const float*)d_in[2];
    const float* w_out   = (const float*)d_in[3];
    const float* sfilter = (const float*)d_in[4];
    float* out = (float*)d_out;

    // keep k_project in the profiler's capture slot (#4)
    k_nop<<<1, 32>>>();
    k_nop<<<1, 32>>>();
    k_nop<<<1, 32>>>();
    k_project<<<dim3(3, NSEG, Bb), 256>>>(x, S);
    k_reduce<<<192, 256>>>();
    k_gemm1<<<dim3(D3 / 64, 4), 256>>>(w_qkv);
    k_gemm2<<<dim3(Dd / 64, Bb), 128>>>(w_out, sfilter);
    k_expand<<<dim3(6, 32, Bb), 256>>>(S, out);
}

// round 9
// speedup vs baseline: 1.6070x; 1.6070x over previous
#include <cuda_runtime.h>
#include <cstdint>

#define Bb   8
#define Tt   4096
#define Dd   768
#define Hh   12
#define HDd  64
#define KSp  32
#define D3   2304

#define NSEG 16
#define TSEG 256
#define TCH  16
#define CHUNKS (TSEG / TCH)   // 16

typedef unsigned long long u64;

// ---------------- scratch ----------------
__device__ float g_partial[NSEG * Bb * KSp * Dd];   // 12.6 MB
__device__ float g_xs[Bb * KSp * Dd];
__device__ float g_qkv[Bb * KSp * D3];
__device__ float g_y[Bb * KSp * Dd];

// ---------------- packed f32x2 ----------------
__device__ __forceinline__ u64 pk2(float lo, float hi) {
    u64 r;
    asm("mov.b64 %0, {%1, %2};" : "=l"(r) : "f"(lo), "f"(hi));
    return r;
}
__device__ __forceinline__ void fma2(u64& d, u64 a, u64 b) {
    asm("fma.rn.f32x2 %0, %1, %2, %0;" : "+l"(d) : "l"(a), "l"(b));
}

// ---------------- tf32 helpers ----------------
__device__ __forceinline__ void tf32_split(float x, uint32_t& hi, uint32_t& lo) {
    uint32_t h;
    asm("cvt.rna.tf32.f32 %0, %1;" : "=r"(h) : "f"(x));
    float r = x - __uint_as_float(h);
    asm("cvt.rna.tf32.f32 %0, %1;" : "=r"(lo) : "f"(r));
    hi = h;
}
__device__ __forceinline__ void mma_tf32(float* c, const uint32_t* a,
                                         const uint32_t* b) {
    asm("mma.sync.aligned.m16n8k8.row.col.f32.tf32.tf32.f32 "
        "{%0,%1,%2,%3}, {%4,%5,%6,%7}, {%8,%9}, {%0,%1,%2,%3};"
        : "+f"(c[0]), "+f"(c[1]), "+f"(c[2]), "+f"(c[3])
        : "r"(a[0]), "r"(a[1]), "r"(a[2]), "r"(a[3]), "r"(b[0]), "r"(b[1]));
}

// =====================================================================
// K1: partial[seg][b][k][d] = sum_{t in seg} S[b,t,k] * x[b,t,d]
// (exact R3 config, measured 48.8us within the 153.6 composite)
// =====================================================================
__global__ void __launch_bounds__(256, 3) k_project(const float* __restrict__ x,
                                                    const float* __restrict__ S) {
    const int d0  = blockIdx.x * 256;
    const int t0  = blockIdx.y * TSEG;
    const int b   = blockIdx.z;
    const int tid = threadIdx.x;

    __shared__ float Ssm[TSEG][KSp];   // 32 KB
    __shared__ float Xsm[TCH][256];    // 16 KB

    const float* xbase = x + ((size_t)b * Tt + t0) * Dd + d0;
    const int lr = tid >> 6;
    const int lc = tid & 63;

    float4 xr[4];
#pragma unroll
    for (int i = 0; i < 4; i++)
        xr[i] = *reinterpret_cast<const float4*>(
            xbase + (size_t)(lr + i * 4) * Dd + lc * 4);

    {
        const float4* sg = reinterpret_cast<const float4*>(
            S + ((size_t)b * Tt + t0) * KSp);
        float4* ss = reinterpret_cast<float4*>(&Ssm[0][0]);
#pragma unroll
        for (int i = 0; i < 8; i++) ss[tid + i * 256] = sg[tid + i * 256];
    }

    const int kq = tid >> 5;
    const int dq = tid & 31;

    u64 acc[4][4];
#pragma unroll
    for (int i = 0; i < 4; i++)
#pragma unroll
        for (int j = 0; j < 4; j++) acc[i][j] = 0ull;

    for (int ch = 0; ch < CHUNKS; ch++) {
#pragma unroll
        for (int i = 0; i < 4; i++)
            *reinterpret_cast<float4*>(&Xsm[lr + i * 4][lc * 4]) = xr[i];
        __syncthreads();
        if (ch + 1 < CHUNKS) {
            const float* nb = xbase + (size_t)(ch + 1) * TCH * Dd;
#pragma unroll
            for (int i = 0; i < 4; i++)
                xr[i] = *reinterpret_cast<const float4*>(
                    nb + (size_t)(lr + i * 4) * Dd + lc * 4);
        }
#pragma unroll
        for (int t = 0; t < TCH; t++) {
            float4 s4 = *reinterpret_cast<const float4*>(&Ssm[ch * TCH + t][kq * 4]);
            u64 sd0 = pk2(s4.x, s4.x), sd1 = pk2(s4.y, s4.y);
            u64 sd2 = pk2(s4.z, s4.z), sd3 = pk2(s4.w, s4.w);
            ulonglong2 xa = *reinterpret_cast<const ulonglong2*>(&Xsm[t][dq * 4]);
            ulonglong2 xb = *reinterpret_cast<const ulonglong2*>(&Xsm[t][128 + dq * 4]);
            fma2(acc[0][0], sd0, xa.x); fma2(acc[0][1], sd0, xa.y);
            fma2(acc[0][2], sd0, xb.x); fma2(acc[0][3], sd0, xb.y);
            fma2(acc[1][0], sd1, xa.x); fma2(acc[1][1], sd1, xa.y);
            fma2(acc[1][2], sd1, xb.x); fma2(acc[1][3], sd1, xb.y);
            fma2(acc[2][0], sd2, xa.x); fma2(acc[2][1], sd2, xa.y);
            fma2(acc[2][2], sd2, xb.x); fma2(acc[2][3], sd2, xb.y);
            fma2(acc[3][0], sd3, xa.x); fma2(acc[3][1], sd3, xa.y);
            fma2(acc[3][2], sd3, xb.x); fma2(acc[3][3], sd3, xb.y);
        }
        __syncthreads();
    }

#pragma unroll
    for (int kk = 0; kk < 4; kk++) {
        float* base = &g_partial[(((size_t)blockIdx.y * Bb + b) * KSp + kq * 4 + kk) * Dd + d0];
        ulonglong2 o1, o2;
        o1.x = acc[kk][0]; o1.y = acc[kk][1];
        o2.x = acc[kk][2]; o2.y = acc[kk][3];
        *reinterpret_cast<ulonglong2*>(base + dq * 4) = o1;
        *reinterpret_cast<ulonglong2*>(base + 128 + dq * 4) = o2;
    }
}

// =====================================================================
// K2: xs = sum over 16 segments
// =====================================================================
__global__ void k_reduce() {
    const int i = blockIdx.x * blockDim.x + threadIdx.x;
    const int stride4 = (Bb * KSp * Dd) / 4;
    const float4* p = reinterpret_cast<const float4*>(g_partial);
    float4 s = make_float4(0.f, 0.f, 0.f, 0.f);
#pragma unroll
    for (int seg = 0; seg < NSEG; seg++) {
        float4 v = p[(size_t)seg * stride4 + i];
        s.x += v.x; s.y += v.y; s.z += v.z; s.w += v.w;
    }
    reinterpret_cast<float4*>(g_xs)[i] = s;
}

// =====================================================================
// K3: qkv[256,2304] = xs[256,768] * w_qkv[2304,768]^T  (153.6 config)
// =====================================================================
__global__ void __launch_bounds__(256) k_gemm1(const float* __restrict__ W) {
    const int n0 = blockIdx.x * 64;
    const int m0 = blockIdx.y * 64;
    const int tid = threadIdx.x;
    const int tn = tid & 15, tm = tid >> 4;
    const int lr = tid >> 3, lc = tid & 7;

    __shared__ float Asm[32][68];
    __shared__ float Bsm[32][68];

    float4 ar[2], br[2];
#pragma unroll
    for (int i = 0; i < 2; i++) {
        ar[i] = *reinterpret_cast<const float4*>(
            &g_xs[(size_t)(m0 + lr + i * 32) * Dd + lc * 4]);
        br[i] = *reinterpret_cast<const float4*>(
            &W[(size_t)(n0 + lr + i * 32) * Dd + lc * 4]);
    }

    u64 acc[4][2];
#pragma unroll
    for (int r = 0; r < 4; r++) { acc[r][0] = 0ull; acc[r][1] = 0ull; }

    for (int d0 = 0; d0 < Dd; d0 += 32) {
#pragma unroll
        for (int i = 0; i < 2; i++) {
            int r = lr + i * 32;
            Asm[lc * 4 + 0][r] = ar[i].x; Asm[lc * 4 + 1][r] = ar[i].y;
            Asm[lc * 4 + 2][r] = ar[i].z; Asm[lc * 4 + 3][r] = ar[i].w;
            Bsm[lc * 4 + 0][r] = br[i].x; Bsm[lc * 4 + 1][r] = br[i].y;
            Bsm[lc * 4 + 2][r] = br[i].z; Bsm[lc * 4 + 3][r] = br[i].w;
        }
        __syncthreads();
        if (d0 + 32 < Dd) {
#pragma unroll
            for (int i = 0; i < 2; i++) {
                ar[i] = *reinterpret_cast<const float4*>(
                    &g_xs[(size_t)(m0 + lr + i * 32) * Dd + d0 + 32 + lc * 4]);
                br[i] = *reinterpret_cast<const float4*>(
                    &W[(size_t)(n0 + lr + i * 32) * Dd + d0 + 32 + lc * 4]);
            }
        }
#pragma unroll
        for (int k = 0; k < 32; k++) {
            float4 av = *reinterpret_cast<const float4*>(&Asm[k][tm * 4]);
            ulonglong2 bv = *reinterpret_cast<const ulonglong2*>(&Bsm[k][tn * 4]);
            u64 a0 = pk2(av.x, av.x), a1 = pk2(av.y, av.y);
            u64 a2 = pk2(av.z, av.z), a3 = pk2(av.w, av.w);
            fma2(acc[0][0], a0, bv.x); fma2(acc[0][1], a0, bv.y);
            fma2(acc[1][0], a1, bv.x); fma2(acc[1][1], a1, bv.y);
            fma2(acc[2][0], a2, bv.x); fma2(acc[2][1], a2, bv.y);
            fma2(acc[3][0], a3, bv.x); fma2(acc[3][1], a3, bv.y);
        }
        __syncthreads();
    }

#pragma unroll
    for (int r = 0; r < 4; r++) {
        ulonglong2 o; o.x = acc[r][0]; o.y = acc[r][1];
        *reinterpret_cast<ulonglong2*>(
            &g_qkv[(size_t)(m0 + tm * 4 + r) * D3 + n0 + tn * 4]) = o;
    }
}

// =====================================================================
// K4: fused FHN + gemm2  (153.6 config)
// =====================================================================
__global__ void __launch_bounds__(128) k_gemm2(const float* __restrict__ W,
                                               const float* __restrict__ sfilter) {
    const int n0 = blockIdx.x * 64;
    const int bb = blockIdx.y;
    const int tid = threadIdx.x;
    const int tn = tid & 15, tm = tid >> 4;
    const int lr = tid >> 3, lc = tid & 7;

    __shared__ float Asm[32][36];
    __shared__ float Bsm[32][68];
    __shared__ float fvs[KSp][Hh];

#pragma unroll
    for (int p = 0; p < 3; p++) {
        int idx = tid + p * 128;
        int m = idx & 31, h = idx >> 5;
        const float4* qp = reinterpret_cast<const float4*>(
            g_qkv + (size_t)(bb * KSp + m) * D3 + h * HDd);
        const float4* kp = reinterpret_cast<const float4*>(
            g_qkv + (size_t)(bb * KSp + m) * D3 + Dd + h * HDd);
        float s = 0.f;
#pragma unroll
        for (int j = 0; j < 16; j++) {
            float4 a = qp[j], c = kp[j];
            s += a.x * c.x + a.y * c.y + a.z * c.z + a.w * c.w;
        }
        float filt = 1.f / (1.f + expf(-sfilter[h * 32 + m]));
        float attn = s * 0.125f * filt;

        float aa = fabsf(attn);
        float scale = fmaxf(aa, 1e-6f);
        float sn = attn / scale;
        float gate = 1.f / (1.f + expf(-(aa - 0.5f) * 10.f));
        float I = sn * (0.1f + 0.9f * gate);
        const float alpha = 1.0f / 12.5f;
        const float denom = 1.0f + alpha * 0.8f;
        float v = 0.f, w = 0.f;
#pragma unroll
        for (int st = 0; st < 2; st++) {
            float dv = v - (v * v * v) * (1.f / 3.f) - w + I;
            float vn = v + dv;
            float wn = (w + (vn + 0.7f) * alpha) / denom;
            v = fminf(fmaxf(vn, -3.f), 3.f);
            w = fminf(fmaxf(wn, -3.f), 3.f);
        }
        fvs[m][h] = v * scale;
    }

    float4 ar[2], br[4];
#pragma unroll
    for (int i = 0; i < 2; i++)
        ar[i] = *reinterpret_cast<const float4*>(
            &g_qkv[(size_t)(bb * KSp + lr + i * 16) * D3 + 2 * Dd + lc * 4]);
#pragma unroll
    for (int i = 0; i < 4; i++)
        br[i] = *reinterpret_cast<const float4*>(
            &W[(size_t)(n0 + lr + i * 16) * Dd + lc * 4]);
    __syncthreads();

    u64 acc[4][2];
#pragma unroll
    for (int r = 0; r < 4; r++) { acc[r][0] = 0ull; acc[r][1] = 0ull; }

    for (int d0 = 0; d0 < Dd; d0 += 32) {
        const int hh = d0 >> 6;
#pragma unroll
        for (int i = 0; i < 2; i++) {
            int r = lr + i * 16;
            float f = fvs[r][hh];
            Asm[lc * 4 + 0][r] = ar[i].x * f; Asm[lc * 4 + 1][r] = ar[i].y * f;
            Asm[lc * 4 + 2][r] = ar[i].z * f; Asm[lc * 4 + 3][r] = ar[i].w * f;
        }
#pragma unroll
        for (int i = 0; i < 4; i++) {
            int r = lr + i * 16;
            Bsm[lc * 4 + 0][r] = br[i].x; Bsm[lc * 4 + 1][r] = br[i].y;
            Bsm[lc * 4 + 2][r] = br[i].z; Bsm[lc * 4 + 3][r] = br[i].w;
        }
        __syncthreads();
        if (d0 + 32 < Dd) {
#pragma unroll
            for (int i = 0; i < 2; i++)
                ar[i] = *reinterpret_cast<const float4*>(
                    &g_qkv[(size_t)(bb * KSp + lr + i * 16) * D3 + 2 * Dd + d0 + 32 + lc * 4]);
#pragma unroll
            for (int i = 0; i < 4; i++)
                br[i] = *reinterpret_cast<const float4*>(
                    &W[(size_t)(n0 + lr + i * 16) * Dd + d0 + 32 + lc * 4]);
        }
#pragma unroll
        for (int k = 0; k < 32; k++) {
            float4 av = *reinterpret_cast<const float4*>(&Asm[k][tm * 4]);
            ulonglong2 bv = *reinterpret_cast<const ulonglong2*>(&Bsm[k][tn * 4]);
            u64 a0 = pk2(av.x, av.x), a1 = pk2(av.y, av.y);
            u64 a2 = pk2(av.z, av.z), a3 = pk2(av.w, av.w);
            fma2(acc[0][0], a0, bv.x); fma2(acc[0][1], a0, bv.y);
            fma2(acc[1][0], a1, bv.x); fma2(acc[1][1], a1, bv.y);
            fma2(acc[2][0], a2, bv.x); fma2(acc[2][1], a2, bv.y);
            fma2(acc[3][0], a3, bv.x); fma2(acc[3][1], a3, bv.y);
        }
        __syncthreads();
    }

#pragma unroll
    for (int r = 0; r < 4; r++) {
        ulonglong2 o; o.x = acc[r][0]; o.y = acc[r][1];
        *reinterpret_cast<ulonglong2*>(
            &g_y[(size_t)(bb * KSp + tm * 4 + r) * Dd + n0 + tn * 4]) = o;
    }
}

// =====================================================================
// K5: out tile [128t x 128e] = S * y via tf32 mma.sync, 3-term split.
// 8 warps: warp tile 32t x 64e. Frag gathers are conflict-free
// (Ssm pad 36 -> bank 4g+tig distinct; Ysm pad 136 -> bank 8tig+g distinct).
// =====================================================================
__global__ void __launch_bounds__(256, 2) k_expand(const float* __restrict__ S,
                                                   float* __restrict__ out) {
    const int e0  = blockIdx.x * 128;
    const int t0  = blockIdx.y * 128;
    const int b   = blockIdx.z;
    const int tid = threadIdx.x;

    __shared__ float Ssm[128][36];     // 18 KB
    __shared__ float Ysm[KSp][136];    // 17.4 KB

    {
        const float4* sg = reinterpret_cast<const float4*>(
            S + ((size_t)b * Tt + t0) * KSp);
#pragma unroll
        for (int i = 0; i < 4; i++) {
            int n = tid + i * 256;
            float4 v = sg[n];
            *reinterpret_cast<float4*>(&Ssm[n >> 3][(n & 7) * 4]) = v;
        }
#pragma unroll
        for (int i = 0; i < 4; i++) {
            int n = tid + i * 256;
            int r = n >> 5, c = n & 31;
            *reinterpret_cast<float4*>(&Ysm[r][c * 4]) =
                *reinterpret_cast<const float4*>(
                    &g_y[((size_t)b * KSp + r) * Dd + e0 + c * 4]);
        }
    }
    __syncthreads();

    const int wid  = tid >> 5;
    const int lane = tid & 31;
    const int tw = (wid >> 1) * 32;    // warp t-offset
    const int ew = (wid & 1) * 64;     // warp e-offset
    const int g   = lane >> 2;
    const int tig = lane & 3;

    float c[2][8][4];
#pragma unroll
    for (int i = 0; i < 2; i++)
#pragma unroll
        for (int j = 0; j < 8; j++)
#pragma unroll
            for (int q = 0; q < 4; q++) c[i][j][q] = 0.f;

#pragma unroll
    for (int ks = 0; ks < 4; ks++) {
        const int k0 = ks * 8;
        uint32_t ahi[2][4], alo[2][4];
#pragma unroll
        for (int mt = 0; mt < 2; mt++) {
            const int mb = tw + mt * 16;
            tf32_split(Ssm[mb + g][k0 + tig],        ahi[mt][0], alo[mt][0]);
            tf32_split(Ssm[mb + g + 8][k0 + tig],    ahi[mt][1], alo[mt][1]);
            tf32_split(Ssm[mb + g][k0 + tig + 4],    ahi[mt][2], alo[mt][2]);
            tf32_split(Ssm[mb + g + 8][k0 + tig + 4],ahi[mt][3], alo[mt][3]);
        }
#pragma unroll
        for (int nt = 0; nt < 8; nt++) {
            const int nb = ew + nt * 8;
            uint32_t bhi[2], blo[2];
            tf32_split(Ysm[k0 + tig][nb + g],     bhi[0], blo[0]);
            tf32_split(Ysm[k0 + tig + 4][nb + g], bhi[1], blo[1]);
#pragma unroll
            for (int mt = 0; mt < 2; mt++) {
                mma_tf32(c[mt][nt], ahi[mt], bhi);
                mma_tf32(c[mt][nt], ahi[mt], blo);
                mma_tf32(c[mt][nt], alo[mt], bhi);
            }
        }
    }

    // epilogue: c0=(g,tig*2), c1=(g,tig*2+1), c2=(g+8,tig*2), c3=(g+8,tig*2+1)
#pragma unroll
    for (int mt = 0; mt < 2; mt++) {
        const int rbase = t0 + tw + mt * 16 + g;
#pragma unroll
        for (int nt = 0; nt < 8; nt++) {
            const int col = e0 + ew + nt * 8 + tig * 2;
            *reinterpret_cast<float2*>(
                &out[((size_t)b * Tt + rbase) * Dd + col]) =
                make_float2(c[mt][nt][0], c[mt][nt][1]);
            *reinterpret_cast<float2*>(
                &out[((size_t)b * Tt + rbase + 8) * Dd + col]) =
                make_float2(c[mt][nt][2], c[mt][nt][3]);
        }
    }
}

// =====================================================================
extern "C" void kernel_launch(void* const* d_in, const int* in_sizes, int n_in,
                              void* d_out, int out_size) {
    const float* x       = (const float*)d_in[0];
    const float* S       = (const float*)d_in[1];
    const float* w_qkv   = (const float*)d_in[2];
    const float* w_out   = (const float*)d_in[3];
    const float* sfilter = (const float*)d_in[4];
    float* out = (float*)d_out;

    k_project<<<dim3(3, NSEG, Bb), 256>>>(x, S);
    k_reduce<<<192, 256>>>();
    k_gemm1<<<dim3(D3 / 64, 4), 256>>>(w_qkv);
    k_gemm2<<<dim3(Dd / 64, Bb), 128>>>(w_out, sfilter);   // capture slot #4
    k_expand<<<dim3(6, 32, Bb), 256>>>(S, out);
}